// round 10
// baseline (speedup 1.0000x reference)
#include <cuda_runtime.h>

#define N 256
#define NPH (N/2 + 2)          // 130 phase layers
#define NSTAGES (N/2)          // 128 stages; stages 1..127 followed by crossing

// Precomputed exp(i*theta) for all layers: [130][256] complex interleaved.
__device__ float2 g_phases[NPH * N];

__global__ void phase_kernel(const float* __restrict__ thetas, int n) {
    int i = blockIdx.x * blockDim.x + threadIdx.x;
    if (i < n) {
        float s, c;
        sincosf(thetas[i], &s, &c);
        g_phases[i] = make_float2(c, s);
    }
}

// One WARP per TWO adjacent columns (phases depend only on the row, so both
// columns share the same per-stage phase loads). Lane l owns rows 8l..8l+7 of
// each column as 4 complex pairs. MMI/phase/MMI are pair-local; the crossing
// has 3 lane-internal couplings plus one complex shuffle exchange per side,
// per column. Output: REAL PART only, row-major float32 [N][N].
__global__ __launch_bounds__(64) void mesh_kernel(float* __restrict__ out) {
    const int lane = threadIdx.x & 31;
    const int wg   = blockIdx.x * 2 + (threadIdx.x >> 5);  // global warp id 0..127
    const int colA = wg * 2;
    const int colB = colA + 1;

    const float AT = sqrtf(0.98f * 0.505f);
    const float AR = sqrtf(0.98f * 0.495f);
    const float CS   = sqrtf(0.98f * 0.01f);
    const float CN   = sqrtf(0.98f * 0.99f);
    const float THRU = CN;                    // pass-through rows 0, N-1

    // Initial states: column c of diag(exp(i*theta[0]))
    float2 XA[4], YA[4], XB[4], YB[4];
    #pragma unroll
    for (int j = 0; j < 4; j++) {
        XA[j] = make_float2(0.f, 0.f); YA[j] = make_float2(0.f, 0.f);
        XB[j] = make_float2(0.f, 0.f); YB[j] = make_float2(0.f, 0.f);
    }
    if ((colA >> 3) == lane) {       // colA even: lands in X slot
        XA[(colA >> 1) & 3] = g_phases[colA];
    }
    if ((colB >> 3) == lane) {       // colB odd: lands in Y slot
        YB[(colB >> 1) & 3] = g_phases[colB];
    }

    // Phase table as float4: one float4 = phases of rows (2m,2m+1).
    const float4* __restrict__ phb = reinterpret_cast<const float4*>(g_phases) + 4 * lane;

    // Prefetch layer 1
    float4 ph[4];
    #pragma unroll
    for (int j = 0; j < 4; j++) ph[j] = phb[128 + j];

    #pragma unroll 1
    for (int s = 1; s <= NSTAGES; s++) {
        // Prefetch next layer (s+1 <= 129 always valid; layer 129 = final diag)
        float4 phn[4];
        #pragma unroll
        for (int j = 0; j < 4; j++) phn[j] = phb[(s + 1) * 128 + j];

        // --- MMI . phase . MMI on each pair, both columns (8-way ILP) ---
        #pragma unroll
        for (int j = 0; j < 4; j++) {
            float4 p = ph[j];
            {   // column A
                float2 x = XA[j], y = YA[j];
                float x1r = AT * x.x - AR * y.y;
                float x1i = AT * x.y + AR * y.x;
                float y1r = AT * y.x - AR * x.y;
                float y1i = AT * y.y + AR * x.x;
                float x2r = p.x * x1r - p.y * x1i;
                float x2i = p.x * x1i + p.y * x1r;
                float y2r = p.z * y1r - p.w * y1i;
                float y2i = p.z * y1i + p.w * y1r;
                XA[j].x = AT * x2r - AR * y2i;
                XA[j].y = AT * x2i + AR * y2r;
                YA[j].x = AT * y2r - AR * x2i;
                YA[j].y = AT * y2i + AR * x2r;
            }
            {   // column B
                float2 x = XB[j], y = YB[j];
                float x1r = AT * x.x - AR * y.y;
                float x1i = AT * x.y + AR * y.x;
                float y1r = AT * y.x - AR * x.y;
                float y1i = AT * y.y + AR * x.x;
                float x2r = p.x * x1r - p.y * x1i;
                float x2i = p.x * x1i + p.y * x1r;
                float y2r = p.z * y1r - p.w * y1i;
                float y2i = p.z * y1i + p.w * y1r;
                XB[j].x = AT * x2r - AR * y2i;
                XB[j].y = AT * x2i + AR * y2r;
                YB[j].x = AT * y2r - AR * x2i;
                YB[j].y = AT * y2i + AR * x2r;
            }
        }

        if (s < NSTAGES) {
            // --- crossing, column A ---
            {
                float xnr = __shfl_down_sync(0xFFFFFFFFu, XA[0].x, 1);
                float xni = __shfl_down_sync(0xFFFFFFFFu, XA[0].y, 1);
                float ypr = __shfl_up_sync  (0xFFFFFFFFu, YA[3].x, 1);
                float ypi = __shfl_up_sync  (0xFFFFFFFFu, YA[3].y, 1);
                float2 nx0, ny3;
                #pragma unroll
                for (int j = 0; j < 3; j++) {
                    float2 yj = YA[j], xj1 = XA[j+1];
                    YA[j].x   = CS * yj.x  - CN * xj1.y;
                    YA[j].y   = CS * yj.y  + CN * xj1.x;
                    XA[j+1].x = CS * xj1.x - CN * yj.y;
                    XA[j+1].y = CS * xj1.y + CN * yj.x;
                }
                if (lane < 31) {
                    ny3.x = CS * YA[3].x - CN * xni;
                    ny3.y = CS * YA[3].y + CN * xnr;
                } else {
                    ny3.x = THRU * YA[3].x;
                    ny3.y = THRU * YA[3].y;
                }
                if (lane > 0) {
                    nx0.x = CS * XA[0].x - CN * ypi;
                    nx0.y = CS * XA[0].y + CN * ypr;
                } else {
                    nx0.x = THRU * XA[0].x;
                    nx0.y = THRU * XA[0].y;
                }
                XA[0] = nx0; YA[3] = ny3;
            }
            // --- crossing, column B ---
            {
                float xnr = __shfl_down_sync(0xFFFFFFFFu, XB[0].x, 1);
                float xni = __shfl_down_sync(0xFFFFFFFFu, XB[0].y, 1);
                float ypr = __shfl_up_sync  (0xFFFFFFFFu, YB[3].x, 1);
                float ypi = __shfl_up_sync  (0xFFFFFFFFu, YB[3].y, 1);
                float2 nx0, ny3;
                #pragma unroll
                for (int j = 0; j < 3; j++) {
                    float2 yj = YB[j], xj1 = XB[j+1];
                    YB[j].x   = CS * yj.x  - CN * xj1.y;
                    YB[j].y   = CS * yj.y  + CN * xj1.x;
                    XB[j+1].x = CS * xj1.x - CN * yj.y;
                    XB[j+1].y = CS * xj1.y + CN * yj.x;
                }
                if (lane < 31) {
                    ny3.x = CS * YB[3].x - CN * xni;
                    ny3.y = CS * YB[3].y + CN * xnr;
                } else {
                    ny3.x = THRU * YB[3].x;
                    ny3.y = THRU * YB[3].y;
                }
                if (lane > 0) {
                    nx0.x = CS * XB[0].x - CN * ypi;
                    nx0.y = CS * XB[0].y + CN * ypr;
                } else {
                    nx0.x = THRU * XB[0].x;
                    nx0.y = THRU * XB[0].y;
                }
                XB[0] = nx0; YB[3] = ny3;
            }
        }

        #pragma unroll
        for (int j = 0; j < 4; j++) ph[j] = phn[j];
    }

    // Final phase layer (129, in ph); store REAL PART only, row-major.
    #pragma unroll
    for (int j = 0; j < 4; j++) {
        float4 p = ph[j];
        int r0 = 8 * lane + 2 * j;
        out[r0 * N + colA]       = p.x * XA[j].x - p.y * XA[j].y;
        out[(r0 + 1) * N + colA] = p.z * YA[j].x - p.w * YA[j].y;
        out[r0 * N + colB]       = p.x * XB[j].x - p.y * XB[j].y;
        out[(r0 + 1) * N + colB] = p.z * YB[j].x - p.w * YB[j].y;
    }
}

extern "C" void kernel_launch(void* const* d_in, const int* in_sizes, int n_in,
                              void* d_out, int out_size) {
    const float* thetas = (const float*)d_in[0];
    int n = in_sizes[0];  // 130 * 256 = 33280

    phase_kernel<<<(n + 255) / 256, 256>>>(thetas, n);
    // 64 CTAs x 64 threads = 128 warps; each warp evolves 2 adjacent columns.
    mesh_kernel<<<N / 4, 64>>>((float*)d_out);
}

// round 11
// speedup vs baseline: 1.8811x; 1.8811x over previous
#include <cuda_runtime.h>

#define N 256
#define NPH (N/2 + 2)          // 130 phase layers
#define NSTAGES (N/2)          // 128 stages; stages 1..127 followed by crossing

// Precomputed exp(i*theta) for all layers: [130][256] complex interleaved.
__device__ float2 g_phases[NPH * N];

__global__ void phase_kernel(const float* __restrict__ thetas, int n) {
    int i = blockIdx.x * blockDim.x + threadIdx.x;
    if (i < n) {
        float s, c;
        sincosf(thetas[i], &s, &c);
        g_phases[i] = make_float2(c, s);
    }
}

// One WARP per column, two warps per CTA (separate SMSPs). Lane l owns rows
// 8l..8l+7 as 4 complex pairs (X[j],Y[j]) in registers. MMI/phase/MMI are
// pair-local (R7-verified math); the crossing has 3 lane-internal couplings
// plus one complex shuffle exchange per side. Phases stream through a
// 4-deep register prefetch ring (16 independent LDG.128 in flight/warp) to
// hide L2 latency. Output: REAL PART only, row-major float32 [N][N].
__global__ __launch_bounds__(64) void mesh_kernel(float* __restrict__ out) {
    const int lane = threadIdx.x & 31;
    const int col  = blockIdx.x * 2 + (threadIdx.x >> 5);

    const float AT = sqrtf(0.98f * 0.505f);
    const float AR = sqrtf(0.98f * 0.495f);
    const float CS   = sqrtf(0.98f * 0.01f);
    const float CN   = sqrtf(0.98f * 0.99f);
    const float THRU = CN;                    // pass-through rows 0, N-1

    // Initial state: column col of diag(exp(i*theta[0]))
    float2 X[4], Y[4];
    #pragma unroll
    for (int j = 0; j < 4; j++) { X[j] = make_float2(0.f, 0.f); Y[j] = make_float2(0.f, 0.f); }
    if ((col >> 3) == lane) {
        float2 p = g_phases[col];
        int j = (col >> 1) & 3;
        if (col & 1) Y[j] = p; else X[j] = p;
    }

    // Phase table as float4: one float4 = phases of rows (2m,2m+1).
    // Layer s, pair j of this lane -> phb[s*128 + j].
    const float4* __restrict__ phb = reinterpret_cast<const float4*>(g_phases) + 4 * lane;

    // 4-slot prefetch ring: before stage s executes, slots hold layers
    // s, s+1, s+2, s+3 (clamped to 129 = final diag layer).
    float4 P0[4], P1[4], P2[4], P3[4];

#define LOADPH(PH, layer) do {                                              \
        int _ly = (layer) <= (NPH - 1) ? (layer) : (NPH - 1);               \
        _Pragma("unroll")                                                   \
        for (int j = 0; j < 4; j++) PH[j] = phb[_ly * 128 + j];             \
    } while (0)

    LOADPH(P0, 1);
    LOADPH(P1, 2);
    LOADPH(P2, 3);
    LOADPH(P3, 4);

    // One mesh stage using phase slot PH (holds layer SCUR); refills PH with
    // layer SCUR+4 right after its last use so 16 loads stay in flight.
#define STEP(SCUR, PH) do {                                                 \
        _Pragma("unroll")                                                   \
        for (int j = 0; j < 4; j++) {                                       \
            float2 x = X[j], y = Y[j];                                      \
            float4 p = PH[j];                                               \
            float x1r = AT * x.x - AR * y.y;                                \
            float x1i = AT * x.y + AR * y.x;                                \
            float y1r = AT * y.x - AR * x.y;                                \
            float y1i = AT * y.y + AR * x.x;                                \
            float x2r = p.x * x1r - p.y * x1i;                              \
            float x2i = p.x * x1i + p.y * x1r;                              \
            float y2r = p.z * y1r - p.w * y1i;                              \
            float y2i = p.z * y1i + p.w * y1r;                              \
            X[j].x = AT * x2r - AR * y2i;                                   \
            X[j].y = AT * x2i + AR * y2r;                                   \
            Y[j].x = AT * y2r - AR * x2i;                                   \
            Y[j].y = AT * y2i + AR * x2r;                                   \
        }                                                                   \
        LOADPH(PH, (SCUR) + 4);                                             \
        if ((SCUR) < NSTAGES) {                                             \
            float xnr = __shfl_down_sync(0xFFFFFFFFu, X[0].x, 1);           \
            float xni = __shfl_down_sync(0xFFFFFFFFu, X[0].y, 1);           \
            float ypr = __shfl_up_sync  (0xFFFFFFFFu, Y[3].x, 1);           \
            float ypi = __shfl_up_sync  (0xFFFFFFFFu, Y[3].y, 1);           \
            float2 nx0, ny3;                                                \
            _Pragma("unroll")                                               \
            for (int j = 0; j < 3; j++) {                                   \
                float2 yj = Y[j], xj1 = X[j+1];                             \
                Y[j].x   = CS * yj.x  - CN * xj1.y;                         \
                Y[j].y   = CS * yj.y  + CN * xj1.x;                         \
                X[j+1].x = CS * xj1.x - CN * yj.y;                          \
                X[j+1].y = CS * xj1.y + CN * yj.x;                          \
            }                                                               \
            if (lane < 31) {                                                \
                ny3.x = CS * Y[3].x - CN * xni;                             \
                ny3.y = CS * Y[3].y + CN * xnr;                             \
            } else {                                                        \
                ny3.x = THRU * Y[3].x;                                      \
                ny3.y = THRU * Y[3].y;                                      \
            }                                                               \
            if (lane > 0) {                                                 \
                nx0.x = CS * X[0].x - CN * ypi;                             \
                nx0.y = CS * X[0].y + CN * ypr;                             \
            } else {                                                        \
                nx0.x = THRU * X[0].x;                                      \
                nx0.y = THRU * X[0].y;                                      \
            }                                                               \
            X[0] = nx0; Y[3] = ny3;                                         \
        }                                                                   \
    } while (0)

    #pragma unroll 1
    for (int s = 1; s <= NSTAGES; s += 4) {
        STEP(s + 0, P0);
        STEP(s + 1, P1);
        STEP(s + 2, P2);
        STEP(s + 3, P3);
    }

    // After s=125 refilled P0 with layer 129 (final diag), epilogue uses P0.
    // Store REAL PART only, row-major [N][N].
    #pragma unroll
    for (int j = 0; j < 4; j++) {
        float4 p = P0[j];
        float xr = p.x * X[j].x - p.y * X[j].y;   // Re(p0 * x)
        float yr = p.z * Y[j].x - p.w * Y[j].y;   // Re(p1 * y)
        int r0 = 8 * lane + 2 * j;
        out[r0 * N + col]       = xr;
        out[(r0 + 1) * N + col] = yr;
    }
}

extern "C" void kernel_launch(void* const* d_in, const int* in_sizes, int n_in,
                              void* d_out, int out_size) {
    const float* thetas = (const float*)d_in[0];
    int n = in_sizes[0];  // 130 * 256 = 33280

    phase_kernel<<<(n + 255) / 256, 256>>>(thetas, n);
    // 128 CTAs x 64 threads: 2 warps/CTA on SMSP 0/1, one column per warp.
    mesh_kernel<<<N / 2, 64>>>((float*)d_out);
}